// round 1
// baseline (speedup 1.0000x reference)
#include <cuda_runtime.h>
#include <math.h>

#define BATCH 512
#define HW 36
#define NPIX 1296            // 36*36
#define NOSC 1296
#define KCON 8
#define STEPS 25

#define FC_M 6144            // 512*12
#define FC_K 3456            // 108*32
#define FC_N 864             // 108*8

#define PHASE_SLICE (BATCH*NOSC)            // 663552
#define PHASE_TOTAL ((STEPS+1)*PHASE_SLICE) // 17252352

// ---------------- scratch (device globals; no allocation allowed) ----------
__device__ float g_c1[BATCH*8*NPIX];
__device__ float g_c2[BATCH*16*NPIX];
__device__ float g_c3[BATCH*32*NPIX];

// ---------------- conv1: 1 -> 8, relu ----------------
__global__ void conv1_kernel(const float* __restrict__ in,
                             const float* __restrict__ w,
                             const float* __restrict__ bias) {
    __shared__ float s[NPIX];
    int b = blockIdx.x;
    for (int i = threadIdx.x; i < NPIX; i += blockDim.x) s[i] = in[b*NPIX + i];
    __syncthreads();
    for (int idx = threadIdx.x; idx < 8*NPIX; idx += blockDim.x) {
        int oc = idx / NPIX, p = idx - oc*NPIX;
        int h = p / HW, x = p - h*HW;
        float acc = bias[oc];
        #pragma unroll
        for (int kh = 0; kh < 3; kh++) {
            int ih = h + kh - 1;
            if ((unsigned)ih >= HW) continue;
            #pragma unroll
            for (int kw = 0; kw < 3; kw++) {
                int iw = x + kw - 1;
                if ((unsigned)iw >= HW) continue;
                acc += s[ih*HW + iw] * w[oc*9 + kh*3 + kw];
            }
        }
        g_c1[b*8*NPIX + idx] = fmaxf(acc, 0.f);
    }
}

// ---------------- conv2: 8 -> 16, relu ----------------
__global__ void conv2_kernel(const float* __restrict__ w,
                             const float* __restrict__ bias) {
    __shared__ float s[8*NPIX];     // 41.5 KB
    __shared__ float ws[16*8*9];
    __shared__ float bs[16];
    int b = blockIdx.x;
    for (int i = threadIdx.x; i < 8*NPIX; i += blockDim.x) s[i] = g_c1[b*8*NPIX + i];
    for (int i = threadIdx.x; i < 16*8*9; i += blockDim.x) ws[i] = w[i];
    if (threadIdx.x < 16) bs[threadIdx.x] = bias[threadIdx.x];
    __syncthreads();
    for (int p = threadIdx.x; p < NPIX; p += blockDim.x) {
        int h = p / HW, x = p - h*HW;
        float acc[16];
        #pragma unroll
        for (int oc = 0; oc < 16; oc++) acc[oc] = bs[oc];
        for (int ic = 0; ic < 8; ic++) {
            float v[9];
            #pragma unroll
            for (int kh = 0; kh < 3; kh++)
                #pragma unroll
                for (int kw = 0; kw < 3; kw++) {
                    int ih = h + kh - 1, iw = x + kw - 1;
                    v[kh*3+kw] = ((unsigned)ih < HW && (unsigned)iw < HW)
                                   ? s[ic*NPIX + ih*HW + iw] : 0.f;
                }
            #pragma unroll
            for (int oc = 0; oc < 16; oc++) {
                const float* wp = &ws[(oc*8 + ic)*9];
                #pragma unroll
                for (int k = 0; k < 9; k++) acc[oc] += v[k]*wp[k];
            }
        }
        #pragma unroll
        for (int oc = 0; oc < 16; oc++)
            g_c2[b*16*NPIX + oc*NPIX + p] = fmaxf(acc[oc], 0.f);
    }
}

// ---------------- conv3: 16 -> 32, sigmoid (dynamic smem: 101,504 B) ------
__global__ void conv3_kernel(const float* __restrict__ w,
                             const float* __restrict__ bias) {
    extern __shared__ float dyn[];
    float* s  = dyn;                 // 16*NPIX
    float* ws = dyn + 16*NPIX;       // 4608
    float* bs = ws + 32*16*9;        // 32
    int b = blockIdx.x;
    for (int i = threadIdx.x; i < 16*NPIX; i += blockDim.x) s[i] = g_c2[b*16*NPIX + i];
    for (int i = threadIdx.x; i < 32*16*9; i += blockDim.x) ws[i] = w[i];
    if (threadIdx.x < 32) bs[threadIdx.x] = bias[threadIdx.x];
    __syncthreads();
    for (int p = threadIdx.x; p < NPIX; p += blockDim.x) {
        int h = p / HW, x = p - h*HW;
        float acc[32];
        #pragma unroll
        for (int oc = 0; oc < 32; oc++) acc[oc] = bs[oc];
        for (int ic = 0; ic < 16; ic++) {
            float v[9];
            #pragma unroll
            for (int kh = 0; kh < 3; kh++)
                #pragma unroll
                for (int kw = 0; kw < 3; kw++) {
                    int ih = h + kh - 1, iw = x + kw - 1;
                    v[kh*3+kw] = ((unsigned)ih < HW && (unsigned)iw < HW)
                                   ? s[ic*NPIX + ih*HW + iw] : 0.f;
                }
            #pragma unroll
            for (int oc = 0; oc < 32; oc++) {
                const float* wp = &ws[(oc*16 + ic)*9];
                #pragma unroll
                for (int k = 0; k < 9; k++) acc[oc] += v[k]*wp[k];
            }
        }
        #pragma unroll
        for (int oc = 0; oc < 32; oc++) {
            float sg = 1.f / (1.f + expf(-acc[oc]));
            g_c3[b*32*NPIX + oc*NPIX + p] = sg;
        }
    }
}

// ---------------- FC GEMM: C[M,N] = A[M,K] * W[N,K]^T + bias --------------
#define BM 64
#define BN 64
#define BK 16
__global__ void gemm_fc(const float* __restrict__ W,
                        const float* __restrict__ bias,
                        float* __restrict__ C) {
    __shared__ float As[BK][BM];
    __shared__ float Bs[BK][BN];
    const float* A = g_c3;
    int tid = threadIdx.x;
    int tx = tid % 16, ty = tid / 16;
    int block_m = blockIdx.y * BM, block_n = blockIdx.x * BN;

    float acc[4][4] = {};
    int arow = tid / 4;            // row within tile (0..63)
    int acol = (tid % 4) * 4;      // k within tile

    for (int k0 = 0; k0 < FC_K; k0 += BK) {
        float4 av = *(const float4*)&A[(size_t)(block_m + arow)*FC_K + k0 + acol];
        As[acol+0][arow] = av.x; As[acol+1][arow] = av.y;
        As[acol+2][arow] = av.z; As[acol+3][arow] = av.w;

        int gn = block_n + arow;
        float4 bv = make_float4(0.f, 0.f, 0.f, 0.f);
        if (gn < FC_N) bv = *(const float4*)&W[(size_t)gn*FC_K + k0 + acol];
        Bs[acol+0][arow] = bv.x; Bs[acol+1][arow] = bv.y;
        Bs[acol+2][arow] = bv.z; Bs[acol+3][arow] = bv.w;
        __syncthreads();

        #pragma unroll
        for (int kk = 0; kk < BK; kk++) {
            float4 a4 = *(const float4*)&As[kk][ty*4];
            float4 b4 = *(const float4*)&Bs[kk][tx*4];
            float a[4] = {a4.x, a4.y, a4.z, a4.w};
            float bb[4] = {b4.x, b4.y, b4.z, b4.w};
            #pragma unroll
            for (int i = 0; i < 4; i++)
                #pragma unroll
                for (int j = 0; j < 4; j++)
                    acc[i][j] += a[i]*bb[j];
        }
        __syncthreads();
    }
    #pragma unroll
    for (int i = 0; i < 4; i++) {
        int gm = block_m + ty*4 + i;
        #pragma unroll
        for (int j = 0; j < 4; j++) {
            int gn = block_n + tx*4 + j;
            if (gn < FC_N)
                C[(size_t)gm*FC_N + gn] = acc[i][j] + bias[gn];
        }
    }
}

// ---------------- Kuramoto step ----------------
__global__ void kuramoto_step(const float* __restrict__ prev,
                              float* __restrict__ next,
                              const float* __restrict__ coup,
                              const int* __restrict__ conn,
                              float ep) {
    int i = blockIdx.x*blockDim.x + threadIdx.x;
    if (i >= BATCH*NOSC) return;
    int b = i / NOSC;
    const float* pb = prev + (size_t)b*NOSC;
    float ph = prev[i];
    const float4* cp = (const float4*)(coup + (size_t)i*KCON);
    const int4*   jp = (const int4*)(conn + (size_t)i*KCON);
    float4 c0 = cp[0], c1 = cp[1];
    int4 j0 = jp[0], j1 = jp[1];
    float acc;
    acc  = c0.x * sinf(__ldg(&pb[j0.x]) - ph);
    acc += c0.y * sinf(__ldg(&pb[j0.y]) - ph);
    acc += c0.z * sinf(__ldg(&pb[j0.z]) - ph);
    acc += c0.w * sinf(__ldg(&pb[j0.w]) - ph);
    acc += c1.x * sinf(__ldg(&pb[j1.x]) - ph);
    acc += c1.y * sinf(__ldg(&pb[j1.y]) - ph);
    acc += c1.z * sinf(__ldg(&pb[j1.z]) - ph);
    acc += c1.w * sinf(__ldg(&pb[j1.w]) - ph);
    next[i] = ph + ep*acc;
}

// ---------------- launch ----------------
extern "C" void kernel_launch(void* const* d_in, const int* in_sizes, int n_in,
                              void* d_out, int out_size) {
    const float* input      = (const float*)d_in[0];
    const float* init_phase = (const float*)d_in[1];
    const int*   conn       = (const int*)  d_in[2];
    // d_in[3] = episodes (fixed 25)
    const float* w1 = (const float*)d_in[4];
    const float* b1 = (const float*)d_in[5];
    const float* w2 = (const float*)d_in[6];
    const float* b2 = (const float*)d_in[7];
    const float* w3 = (const float*)d_in[8];
    const float* b3 = (const float*)d_in[9];
    const float* fw = (const float*)d_in[10];
    const float* fb = (const float*)d_in[11];

    float* out   = (float*)d_out;
    float* fcout = out + PHASE_TOTAL;   // coupling [512,1296,8]

    conv1_kernel<<<BATCH, 256>>>(input, w1, b1);
    conv2_kernel<<<BATCH, 256>>>(w2, b2);

    int c3_smem = (16*NPIX + 32*16*9 + 32) * (int)sizeof(float);
    cudaFuncSetAttribute(conv3_kernel, cudaFuncAttributeMaxDynamicSharedMemorySize, c3_smem);
    conv3_kernel<<<BATCH, 256, c3_smem>>>(w3, b3);

    dim3 ggrid((FC_N + BN - 1)/BN, FC_M/BM);
    gemm_fc<<<ggrid, 256>>>(fw, fb, fcout);

    // phase trajectory slice 0 = initial phase
    cudaMemcpyAsync(out, init_phase, (size_t)PHASE_SLICE*sizeof(float),
                    cudaMemcpyDeviceToDevice);

    float ep = 0.1f;
    int threads = 256;
    int blocks = (BATCH*NOSC + threads - 1)/threads;
    for (int i = 0; i < STEPS; i++) {
        kuramoto_step<<<blocks, threads>>>(out + (size_t)i*PHASE_SLICE,
                                           out + (size_t)(i+1)*PHASE_SLICE,
                                           fcout, conn, ep);
        ep = ep - (0.5f*(float)i)*ep/25.0f;
    }
}

// round 3
// speedup vs baseline: 1.1908x; 1.1908x over previous
#include <cuda_runtime.h>
#include <math.h>

#define BATCH 512
#define HW 36
#define NPIX 1296
#define NOSC 1296
#define KCON 8
#define STEPS 25

#define FC_M 6144
#define FC_K 3456
#define FC_N 864

#define PHASE_SLICE (BATCH*NOSC)
#define PHASE_TOTAL ((STEPS+1)*PHASE_SLICE)

// ---------------- scratch ----------------
__device__ float g_c1[BATCH*8*NPIX];
__device__ float g_c2[BATCH*16*NPIX];
__device__ float g_c3[BATCH*32*NPIX];

// ---------------- conv1: 1 -> 8, relu ----------------
__global__ void conv1_kernel(const float* __restrict__ in,
                             const float* __restrict__ w,
                             const float* __restrict__ bias) {
    __shared__ float s[NPIX];
    int b = blockIdx.x;
    for (int i = threadIdx.x; i < NPIX; i += blockDim.x) s[i] = in[b*NPIX + i];
    __syncthreads();
    for (int idx = threadIdx.x; idx < 8*NPIX; idx += blockDim.x) {
        int oc = idx / NPIX, p = idx - oc*NPIX;
        int h = p / HW, x = p - h*HW;
        float acc = bias[oc];
        #pragma unroll
        for (int kh = 0; kh < 3; kh++) {
            int ih = h + kh - 1;
            if ((unsigned)ih >= HW) continue;
            #pragma unroll
            for (int kw = 0; kw < 3; kw++) {
                int iw = x + kw - 1;
                if ((unsigned)iw >= HW) continue;
                acc += s[ih*HW + iw] * w[oc*9 + kh*3 + kw];
            }
        }
        g_c1[b*8*NPIX + idx] = fmaxf(acc, 0.f);
    }
}

// ---------------- conv2: 8 -> 16, relu ----------------
__global__ void conv2_kernel(const float* __restrict__ w,
                             const float* __restrict__ bias) {
    __shared__ float s[8*NPIX];
    __shared__ float ws[16*8*9];
    __shared__ float bs[16];
    int b = blockIdx.x;
    for (int i = threadIdx.x; i < 8*NPIX; i += blockDim.x) s[i] = g_c1[b*8*NPIX + i];
    for (int i = threadIdx.x; i < 16*8*9; i += blockDim.x) ws[i] = w[i];
    if (threadIdx.x < 16) bs[threadIdx.x] = bias[threadIdx.x];
    __syncthreads();
    for (int p = threadIdx.x; p < NPIX; p += blockDim.x) {
        int h = p / HW, x = p - h*HW;
        float acc[16];
        #pragma unroll
        for (int oc = 0; oc < 16; oc++) acc[oc] = bs[oc];
        for (int ic = 0; ic < 8; ic++) {
            float v[9];
            #pragma unroll
            for (int kh = 0; kh < 3; kh++)
                #pragma unroll
                for (int kw = 0; kw < 3; kw++) {
                    int ih = h + kh - 1, iw = x + kw - 1;
                    v[kh*3+kw] = ((unsigned)ih < HW && (unsigned)iw < HW)
                                   ? s[ic*NPIX + ih*HW + iw] : 0.f;
                }
            #pragma unroll
            for (int oc = 0; oc < 16; oc++) {
                const float* wp = &ws[(oc*8 + ic)*9];
                #pragma unroll
                for (int k = 0; k < 9; k++) acc[oc] += v[k]*wp[k];
            }
        }
        #pragma unroll
        for (int oc = 0; oc < 16; oc++)
            g_c2[b*16*NPIX + oc*NPIX + p] = fmaxf(acc[oc], 0.f);
    }
}

// ---------------- conv3: 16 -> 32, sigmoid ----------------
__global__ void conv3_kernel(const float* __restrict__ w,
                             const float* __restrict__ bias) {
    extern __shared__ float dyn[];
    float* s  = dyn;
    float* ws = dyn + 16*NPIX;
    float* bs = ws + 32*16*9;
    int b = blockIdx.x;
    for (int i = threadIdx.x; i < 16*NPIX; i += blockDim.x) s[i] = g_c2[b*16*NPIX + i];
    for (int i = threadIdx.x; i < 32*16*9; i += blockDim.x) ws[i] = w[i];
    if (threadIdx.x < 32) bs[threadIdx.x] = bias[threadIdx.x];
    __syncthreads();
    for (int p = threadIdx.x; p < NPIX; p += blockDim.x) {
        int h = p / HW, x = p - h*HW;
        float acc[32];
        #pragma unroll
        for (int oc = 0; oc < 32; oc++) acc[oc] = bs[oc];
        for (int ic = 0; ic < 16; ic++) {
            float v[9];
            #pragma unroll
            for (int kh = 0; kh < 3; kh++)
                #pragma unroll
                for (int kw = 0; kw < 3; kw++) {
                    int ih = h + kh - 1, iw = x + kw - 1;
                    v[kh*3+kw] = ((unsigned)ih < HW && (unsigned)iw < HW)
                                   ? s[ic*NPIX + ih*HW + iw] : 0.f;
                }
            #pragma unroll
            for (int oc = 0; oc < 32; oc++) {
                const float* wp = &ws[(oc*16 + ic)*9];
                #pragma unroll
                for (int k = 0; k < 9; k++) acc[oc] += v[k]*wp[k];
            }
        }
        #pragma unroll
        for (int oc = 0; oc < 32; oc++) {
            float sg = 1.f / (1.f + expf(-acc[oc]));
            g_c3[b*32*NPIX + oc*NPIX + p] = sg;
        }
    }
}

// ---------------- FC GEMM: C[M,N] = A[M,K] * W[N,K]^T + bias --------------
// 128x96 block tile, 8x6 micro-tile, BK=32, register-staged prefetch.
#define BM 128
#define BN 96
#define BK 32
#define APAD 4
#define BPAD 4
__global__ void __launch_bounds__(256, 2)
gemm_fc(const float* __restrict__ W,
        const float* __restrict__ bias,
        float* __restrict__ C) {
    __shared__ float As[BK][BM+APAD];   // 32x132
    __shared__ float Bs[BK][BN+BPAD];   // 32x100
    const float* A = g_c3;
    int tid = threadIdx.x;
    int tx = tid % 16;          // 0..15 -> 6 cols each
    int ty = tid / 16;          // 0..15 -> 8 rows each
    int block_m = blockIdx.y * BM;
    int block_n = blockIdx.x * BN;

    float acc[8][6] = {};
    float4 pa[4], pb[3];

    // f4 index -> (row, kcol): 8 float4 per row of 32 k
    #pragma unroll
    for (int j = 0; j < 4; j++) {
        int f = tid + j*256;
        int row = f >> 3, kc = (f & 7) * 4;
        pa[j] = *(const float4*)&A[(size_t)(block_m + row)*FC_K + kc];
    }
    #pragma unroll
    for (int j = 0; j < 3; j++) {
        int f = tid + j*256;
        int row = f >> 3, kc = (f & 7) * 4;
        pb[j] = *(const float4*)&W[(size_t)(block_n + row)*FC_K + kc];
    }

    for (int k0 = 0; k0 < FC_K; k0 += BK) {
        // stage prefetched regs into smem
        #pragma unroll
        for (int j = 0; j < 4; j++) {
            int f = tid + j*256;
            int row = f >> 3, kc = (f & 7) * 4;
            As[kc+0][row] = pa[j].x; As[kc+1][row] = pa[j].y;
            As[kc+2][row] = pa[j].z; As[kc+3][row] = pa[j].w;
        }
        #pragma unroll
        for (int j = 0; j < 3; j++) {
            int f = tid + j*256;
            int row = f >> 3, kc = (f & 7) * 4;
            Bs[kc+0][row] = pb[j].x; Bs[kc+1][row] = pb[j].y;
            Bs[kc+2][row] = pb[j].z; Bs[kc+3][row] = pb[j].w;
        }
        __syncthreads();

        // prefetch next tile
        int k1 = k0 + BK;
        if (k1 < FC_K) {
            #pragma unroll
            for (int j = 0; j < 4; j++) {
                int f = tid + j*256;
                int row = f >> 3, kc = (f & 7) * 4;
                pa[j] = *(const float4*)&A[(size_t)(block_m + row)*FC_K + k1 + kc];
            }
            #pragma unroll
            for (int j = 0; j < 3; j++) {
                int f = tid + j*256;
                int row = f >> 3, kc = (f & 7) * 4;
                pb[j] = *(const float4*)&W[(size_t)(block_n + row)*FC_K + k1 + kc];
            }
        }

        #pragma unroll
        for (int kk = 0; kk < BK; kk++) {
            float4 a0 = *(const float4*)&As[kk][ty*8];
            float4 a1 = *(const float4*)&As[kk][ty*8+4];
            float2 b0 = *(const float2*)&Bs[kk][tx*6];
            float2 b1 = *(const float2*)&Bs[kk][tx*6+2];
            float2 b2 = *(const float2*)&Bs[kk][tx*6+4];
            float a[8] = {a0.x,a0.y,a0.z,a0.w,a1.x,a1.y,a1.z,a1.w};
            float bb[6] = {b0.x,b0.y,b1.x,b1.y,b2.x,b2.y};
            #pragma unroll
            for (int i = 0; i < 8; i++)
                #pragma unroll
                for (int j = 0; j < 6; j++)
                    acc[i][j] += a[i]*bb[j];
        }
        __syncthreads();
    }

    #pragma unroll
    for (int i = 0; i < 8; i++) {
        int gm = block_m + ty*8 + i;
        #pragma unroll
        for (int j = 0; j < 6; j++) {
            int gn = block_n + tx*6 + j;
            C[(size_t)gm*FC_N + gn] = acc[i][j] + bias[gn];
        }
    }
}

// ---------------- fused Kuramoto: all 25 steps, one block per batch -------
__global__ void kuramoto_all(const float* __restrict__ init,
                             float* __restrict__ out,
                             const float* __restrict__ coup,
                             const int* __restrict__ conn) {
    extern __shared__ char dynraw[];
    float* sc  = (float*)dynraw;                 // [NOSC*KCON]
    int*   sj  = (int*)(sc + NOSC*KCON);         // [NOSC*KCON]
    float* ph0 = (float*)(sj + NOSC*KCON);       // [NOSC]
    float* ph1 = ph0 + NOSC;                     // [NOSC]

    int b = blockIdx.x;
    int tid = threadIdx.x;
    const float* cb = coup + (size_t)b*NOSC*KCON;
    const int*   jb = conn + (size_t)b*NOSC*KCON;

    for (int i = tid; i < NOSC*KCON; i += blockDim.x) {
        sc[i] = cb[i];
        sj[i] = jb[i];
    }
    for (int i = tid; i < NOSC; i += blockDim.x) {
        float p = init[(size_t)b*NOSC + i];
        ph0[i] = p;
        out[(size_t)b*NOSC + i] = p;     // slice 0 = initial phase
    }
    __syncthreads();

    float ep = 0.1f;
    float* cur = ph0;
    float* nxt = ph1;
    for (int s = 0; s < STEPS; s++) {
        float* dst = out + (size_t)(s+1)*PHASE_SLICE + (size_t)b*NOSC;
        for (int i = tid; i < NOSC; i += blockDim.x) {
            float p = cur[i];
            float acc = 0.f;
            #pragma unroll
            for (int k = 0; k < KCON; k++) {
                acc += sc[i*KCON + k] * sinf(cur[sj[i*KCON + k]] - p);
            }
            float np = p + ep*acc;
            nxt[i] = np;
            dst[i] = np;
        }
        ep = ep - (0.5f*(float)s)*ep/25.0f;
        float* t = cur; cur = nxt; nxt = t;
        __syncthreads();
    }
}

// ---------------- launch ----------------
extern "C" void kernel_launch(void* const* d_in, const int* in_sizes, int n_in,
                              void* d_out, int out_size) {
    const float* input      = (const float*)d_in[0];
    const float* init_phase = (const float*)d_in[1];
    const int*   conn       = (const int*)  d_in[2];
    const float* w1 = (const float*)d_in[4];
    const float* b1 = (const float*)d_in[5];
    const float* w2 = (const float*)d_in[6];
    const float* b2 = (const float*)d_in[7];
    const float* w3 = (const float*)d_in[8];
    const float* b3 = (const float*)d_in[9];
    const float* fw = (const float*)d_in[10];
    const float* fb = (const float*)d_in[11];

    float* out   = (float*)d_out;
    float* fcout = out + PHASE_TOTAL;

    conv1_kernel<<<BATCH, 256>>>(input, w1, b1);
    conv2_kernel<<<BATCH, 256>>>(w2, b2);

    int c3_smem = (16*NPIX + 32*16*9 + 32) * (int)sizeof(float);
    cudaFuncSetAttribute(conv3_kernel, cudaFuncAttributeMaxDynamicSharedMemorySize, c3_smem);
    conv3_kernel<<<BATCH, 256, c3_smem>>>(w3, b3);

    dim3 ggrid(FC_N/BN, FC_M/BM);
    gemm_fc<<<ggrid, 256>>>(fw, fb, fcout);

    int ksmem = (NOSC*KCON)*(int)sizeof(float) + (NOSC*KCON)*(int)sizeof(int)
              + 2*NOSC*(int)sizeof(float);
    cudaFuncSetAttribute(kuramoto_all, cudaFuncAttributeMaxDynamicSharedMemorySize, ksmem);
    kuramoto_all<<<BATCH, 512, ksmem>>>(init_phase, out, fcout, conn);
}

// round 5
// speedup vs baseline: 1.5120x; 1.2697x over previous
#include <cuda_runtime.h>
#include <cuda_bf16.h>
#include <math.h>
#include <stdint.h>

#define BATCH 512
#define HW 36
#define NPIX 1296
#define NOSC 1296
#define KCON 8
#define STEPS 25

#define FC_M 6144
#define FC_K 3456
#define FC_N 864

#define PHASE_SLICE (BATCH*NOSC)
#define PHASE_TOTAL ((STEPS+1)*PHASE_SLICE)

// ---------------- scratch ----------------
__device__ float g_c1[BATCH*8*NPIX];
__device__ float g_c2[BATCH*16*NPIX];
__device__ __nv_bfloat16 g_ah[(size_t)FC_M*FC_K];
__device__ __nv_bfloat16 g_al[(size_t)FC_M*FC_K];
__device__ __nv_bfloat16 g_wh[(size_t)FC_N*FC_K];
__device__ __nv_bfloat16 g_wl[(size_t)FC_N*FC_K];

__device__ __forceinline__ uint32_t smem_u32(const void* p) {
    uint32_t a;
    asm("{ .reg .u64 t; cvta.to.shared.u64 t, %1; cvt.u32.u64 %0, t; }"
        : "=r"(a) : "l"(p));
    return a;
}
#define LDS32(v, addr) \
    asm volatile("ld.shared.b32 %0, [%1];" : "=r"(v) : "r"(addr))
#define MMA16816(d, a0,a1,a2,a3, b0,b1) \
    asm volatile("mma.sync.aligned.m16n8k16.row.col.f32.bf16.bf16.f32 " \
        "{%0,%1,%2,%3}, {%4,%5,%6,%7}, {%8,%9}, {%0,%1,%2,%3};" \
        : "+f"((d)[0]),"+f"((d)[1]),"+f"((d)[2]),"+f"((d)[3]) \
        : "r"(a0),"r"(a1),"r"(a2),"r"(a3),"r"(b0),"r"(b1))

// ---------------- conv1: 1 -> 8, relu ----------------
__global__ void conv1_kernel(const float* __restrict__ in,
                             const float* __restrict__ w,
                             const float* __restrict__ bias) {
    __shared__ float s[NPIX];
    int b = blockIdx.x;
    for (int i = threadIdx.x; i < NPIX; i += blockDim.x) s[i] = in[b*NPIX + i];
    __syncthreads();
    for (int idx = threadIdx.x; idx < 8*NPIX; idx += blockDim.x) {
        int oc = idx / NPIX, p = idx - oc*NPIX;
        int h = p / HW, x = p - h*HW;
        float acc = bias[oc];
        #pragma unroll
        for (int kh = 0; kh < 3; kh++) {
            int ih = h + kh - 1;
            if ((unsigned)ih >= HW) continue;
            #pragma unroll
            for (int kw = 0; kw < 3; kw++) {
                int iw = x + kw - 1;
                if ((unsigned)iw >= HW) continue;
                acc += s[ih*HW + iw] * w[oc*9 + kh*3 + kw];
            }
        }
        g_c1[b*8*NPIX + idx] = fmaxf(acc, 0.f);
    }
}

// ---------------- conv2: 8 -> 16, relu ----------------
__global__ void conv2_kernel(const float* __restrict__ w,
                             const float* __restrict__ bias) {
    __shared__ float s[8*NPIX];
    __shared__ float ws[16*8*9];
    __shared__ float bs[16];
    int b = blockIdx.x;
    for (int i = threadIdx.x; i < 8*NPIX; i += blockDim.x) s[i] = g_c1[b*8*NPIX + i];
    for (int i = threadIdx.x; i < 16*8*9; i += blockDim.x) ws[i] = w[i];
    if (threadIdx.x < 16) bs[threadIdx.x] = bias[threadIdx.x];
    __syncthreads();
    for (int p = threadIdx.x; p < NPIX; p += blockDim.x) {
        int h = p / HW, x = p - h*HW;
        float acc[16];
        #pragma unroll
        for (int oc = 0; oc < 16; oc++) acc[oc] = bs[oc];
        for (int ic = 0; ic < 8; ic++) {
            float v[9];
            #pragma unroll
            for (int kh = 0; kh < 3; kh++)
                #pragma unroll
                for (int kw = 0; kw < 3; kw++) {
                    int ih = h + kh - 1, iw = x + kw - 1;
                    v[kh*3+kw] = ((unsigned)ih < HW && (unsigned)iw < HW)
                                   ? s[ic*NPIX + ih*HW + iw] : 0.f;
                }
            #pragma unroll
            for (int oc = 0; oc < 16; oc++) {
                const float* wp = &ws[(oc*8 + ic)*9];
                #pragma unroll
                for (int k = 0; k < 9; k++) acc[oc] += v[k]*wp[k];
            }
        }
        #pragma unroll
        for (int oc = 0; oc < 16; oc++)
            g_c2[b*16*NPIX + oc*NPIX + p] = fmaxf(acc[oc], 0.f);
    }
}

// ---------------- conv3: 16 -> 32, sigmoid, writes bf16 hi/lo split -------
__global__ void conv3_kernel(const float* __restrict__ w,
                             const float* __restrict__ bias) {
    extern __shared__ float dyn[];
    float* s  = dyn;
    float* ws = dyn + 16*NPIX;
    float* bs = ws + 32*16*9;
    int b = blockIdx.x;
    for (int i = threadIdx.x; i < 16*NPIX; i += blockDim.x) s[i] = g_c2[b*16*NPIX + i];
    for (int i = threadIdx.x; i < 32*16*9; i += blockDim.x) ws[i] = w[i];
    if (threadIdx.x < 32) bs[threadIdx.x] = bias[threadIdx.x];
    __syncthreads();
    for (int p = threadIdx.x; p < NPIX; p += blockDim.x) {
        int h = p / HW, x = p - h*HW;
        float acc[32];
        #pragma unroll
        for (int oc = 0; oc < 32; oc++) acc[oc] = bs[oc];
        for (int ic = 0; ic < 16; ic++) {
            float v[9];
            #pragma unroll
            for (int kh = 0; kh < 3; kh++)
                #pragma unroll
                for (int kw = 0; kw < 3; kw++) {
                    int ih = h + kh - 1, iw = x + kw - 1;
                    v[kh*3+kw] = ((unsigned)ih < HW && (unsigned)iw < HW)
                                   ? s[ic*NPIX + ih*HW + iw] : 0.f;
                }
            #pragma unroll
            for (int oc = 0; oc < 32; oc++) {
                const float* wp = &ws[(oc*16 + ic)*9];
                #pragma unroll
                for (int k = 0; k < 9; k++) acc[oc] += v[k]*wp[k];
            }
        }
        #pragma unroll
        for (int oc = 0; oc < 32; oc++) {
            float sg = 1.f / (1.f + expf(-acc[oc]));
            size_t idx = (size_t)b*32*NPIX + (size_t)oc*NPIX + p;
            __nv_bfloat16 hi = __float2bfloat16(sg);
            float lo = sg - __bfloat162float(hi);
            g_ah[idx] = hi;
            g_al[idx] = __float2bfloat16(lo);
        }
    }
}

// ---------------- W split: fp32 -> bf16 hi/lo ----------------
__global__ void split_w_kernel(const float* __restrict__ W) {
    int i = blockIdx.x*blockDim.x + threadIdx.x;
    if (i < FC_N*FC_K) {
        float x = W[i];
        __nv_bfloat16 h = __float2bfloat16(x);
        g_wh[i] = h;
        g_wl[i] = __float2bfloat16(x - __bfloat162float(h));
    }
}

// ---------------- warp-MMA FC GEMM (portable mma.sync, bf16 3-pass) -------
// C[6144,864] = A * W^T + bias;  passes: Ah*Wh + Ah*Wl + Al*Wh
#define BM 128
#define BN 96
#define NCH 54               // 3456/64 chunks of 64 bf16
#define GM_ITERS (3*NCH)     // 162
#define AROW 144             // 64 bf16 = 128B + 16B pad
#define ABUF (128*AROW)      // 18432
#define BBUF (96*AROW)       // 13824
#define GM_SMEM (2*ABUF + 2*BBUF)

__global__ void __launch_bounds__(256, 2)
gemm_fc_mma(const float* __restrict__ bias, float* __restrict__ C) {
    extern __shared__ char sm[];
    uint32_t saA = smem_u32(sm);
    uint32_t saB = saA + 2*ABUF;

    int tid = threadIdx.x;
    int wid = tid >> 5, lane = tid & 31;
    int g = lane >> 2, q = lane & 3;
    int wm = wid >> 1;           // 0..3 -> m offset wm*32
    int wn = wid & 1;            // 0..1 -> n offset wn*48
    int block_m = blockIdx.y * BM;
    int block_n = blockIdx.x * BN;

    float acc[2][6][4] = {};

    auto issue = [&](int it, int buf) {
        int pass = it / NCH;
        int kc = it - pass*NCH;
        const char* Ab = (const char*)(pass == 2 ? g_al : g_ah)
                       + (size_t)block_m*6912 + (size_t)kc*128;
        const char* Bb = (const char*)(pass == 1 ? g_wl : g_wh)
                       + (size_t)block_n*6912 + (size_t)kc*128;
        uint32_t da = saA + buf*ABUF;
        uint32_t db = saB + buf*BBUF;
        #pragma unroll
        for (int j = 0; j < 4; j++) {
            int slot = tid + j*256;
            int r = slot >> 3, seg = slot & 7;
            uint32_t d = da + r*AROW + seg*16;
            const char* s = Ab + (size_t)r*6912 + seg*16;
            asm volatile("cp.async.cg.shared.global [%0], [%1], 16;"
                         :: "r"(d), "l"(s));
        }
        #pragma unroll
        for (int j = 0; j < 3; j++) {
            int slot = tid + j*256;
            int r = slot >> 3, seg = slot & 7;
            uint32_t d = db + r*AROW + seg*16;
            const char* s = Bb + (size_t)r*6912 + seg*16;
            asm volatile("cp.async.cg.shared.global [%0], [%1], 16;"
                         :: "r"(d), "l"(s));
        }
        asm volatile("cp.async.commit_group;" ::: "memory");
    };

    issue(0, 0);
    for (int it = 0; it < GM_ITERS; it++) {
        int cur = it & 1;
        if (it + 1 < GM_ITERS) {
            issue(it + 1, 1 - cur);
            asm volatile("cp.async.wait_group 1;" ::: "memory");
        } else {
            asm volatile("cp.async.wait_group 0;" ::: "memory");
        }
        __syncthreads();

        uint32_t ab = saA + cur*ABUF;
        uint32_t bb = saB + cur*BBUF;
        #pragma unroll
        for (int kk = 0; kk < 4; kk++) {
            uint32_t koff = kk*32 + q*4;
            uint32_t bf[6][2];
            #pragma unroll
            for (int nt = 0; nt < 6; nt++) {
                uint32_t addr = bb + (uint32_t)(wn*48 + nt*8 + g)*AROW + koff;
                LDS32(bf[nt][0], addr);
                LDS32(bf[nt][1], addr + 16);
            }
            #pragma unroll
            for (int mt = 0; mt < 2; mt++) {
                uint32_t base = ab + (uint32_t)(wm*32 + mt*16 + g)*AROW + koff;
                uint32_t a0, a1, a2, a3;
                LDS32(a0, base);
                LDS32(a2, base + 16);
                LDS32(a1, base + 8*AROW);
                LDS32(a3, base + 8*AROW + 16);
                #pragma unroll
                for (int nt = 0; nt < 6; nt++)
                    MMA16816(acc[mt][nt], a0, a1, a2, a3, bf[nt][0], bf[nt][1]);
            }
        }
        __syncthreads();
    }

    // epilogue
    #pragma unroll
    for (int mt = 0; mt < 2; mt++) {
        int row = block_m + wm*32 + mt*16 + g;
        #pragma unroll
        for (int nt = 0; nt < 6; nt++) {
            int col = block_n + wn*48 + nt*8 + 2*q;
            float bv0 = bias[col], bv1 = bias[col+1];
            float2 v0 = make_float2(acc[mt][nt][0] + bv0, acc[mt][nt][1] + bv1);
            float2 v1 = make_float2(acc[mt][nt][2] + bv0, acc[mt][nt][3] + bv1);
            *(float2*)&C[(size_t)row*FC_N + col] = v0;
            *(float2*)&C[(size_t)(row+8)*FC_N + col] = v1;
        }
    }
}

// ---------------- fused Kuramoto: all 25 steps, one block per batch -------
__global__ void kuramoto_all(const float* __restrict__ init,
                             float* __restrict__ out,
                             const float* __restrict__ coup,
                             const int* __restrict__ conn) {
    extern __shared__ char dynraw[];
    float* sc  = (float*)dynraw;
    int*   sj  = (int*)(sc + NOSC*KCON);
    float* ph0 = (float*)(sj + NOSC*KCON);
    float* ph1 = ph0 + NOSC;

    int b = blockIdx.x;
    int tid = threadIdx.x;
    const float* cb = coup + (size_t)b*NOSC*KCON;
    const int*   jb = conn + (size_t)b*NOSC*KCON;

    for (int i = tid; i < NOSC*KCON; i += blockDim.x) {
        sc[i] = cb[i];
        sj[i] = jb[i];
    }
    for (int i = tid; i < NOSC; i += blockDim.x) {
        float p = init[(size_t)b*NOSC + i];
        ph0[i] = p;
        out[(size_t)b*NOSC + i] = p;
    }
    __syncthreads();

    float ep = 0.1f;
    float* cur = ph0;
    float* nxt = ph1;
    for (int s = 0; s < STEPS; s++) {
        float* dst = out + (size_t)(s+1)*PHASE_SLICE + (size_t)b*NOSC;
        for (int i = tid; i < NOSC; i += blockDim.x) {
            float p = cur[i];
            float acc = 0.f;
            #pragma unroll
            for (int k = 0; k < KCON; k++) {
                acc += sc[i*KCON + k] * sinf(cur[sj[i*KCON + k]] - p);
            }
            float np = p + ep*acc;
            nxt[i] = np;
            dst[i] = np;
        }
        ep = ep - (0.5f*(float)s)*ep/25.0f;
        float* t = cur; cur = nxt; nxt = t;
        __syncthreads();
    }
}

// ---------------- launch ----------------
extern "C" void kernel_launch(void* const* d_in, const int* in_sizes, int n_in,
                              void* d_out, int out_size) {
    const float* input      = (const float*)d_in[0];
    const float* init_phase = (const float*)d_in[1];
    const int*   conn       = (const int*)  d_in[2];
    const float* w1 = (const float*)d_in[4];
    const float* b1 = (const float*)d_in[5];
    const float* w2 = (const float*)d_in[6];
    const float* b2 = (const float*)d_in[7];
    const float* w3 = (const float*)d_in[8];
    const float* b3 = (const float*)d_in[9];
    const float* fw = (const float*)d_in[10];
    const float* fb = (const float*)d_in[11];

    float* out   = (float*)d_out;
    float* fcout = out + PHASE_TOTAL;

    conv1_kernel<<<BATCH, 256>>>(input, w1, b1);

    split_w_kernel<<<(FC_N*FC_K + 255)/256, 256>>>(fw);

    conv2_kernel<<<BATCH, 512>>>(w2, b2);

    int c3_smem = (16*NPIX + 32*16*9 + 32) * (int)sizeof(float);
    cudaFuncSetAttribute(conv3_kernel, cudaFuncAttributeMaxDynamicSharedMemorySize, c3_smem);
    conv3_kernel<<<BATCH, 512, c3_smem>>>(w3, b3);

    cudaFuncSetAttribute(gemm_fc_mma, cudaFuncAttributeMaxDynamicSharedMemorySize, GM_SMEM);
    dim3 ggrid(FC_N/BN, FC_M/BM);   // (9, 48)
    gemm_fc_mma<<<ggrid, 256, GM_SMEM>>>(fb, fcout);

    int ksmem = (NOSC*KCON)*(int)sizeof(float) + (NOSC*KCON)*(int)sizeof(int)
              + 2*NOSC*(int)sizeof(float);
    cudaFuncSetAttribute(kuramoto_all, cudaFuncAttributeMaxDynamicSharedMemorySize, ksmem);
    kuramoto_all<<<BATCH, 512, ksmem>>>(init_phase, out, fcout, conn);
}